// round 10
// baseline (speedup 1.0000x reference)
#include <cuda_runtime.h>
#include <cstdint>

#define BB 16
#define NN 25200
#define NCLS 80
#define STRIDE 85
#define TOPK 1024
#define MAXDET 300
#define CONF_THRES 0.25f
#define IOU_THR 0.45f
#define MAX_WH 7680.0f
#define BND_CAP 2048
#define BLK_ANCH 64
#define BLKS_PER_B 394      // ceil(25200/64)

// -------- scratch (device globals, no allocations) --------
__device__ unsigned long long g_keys[BB * NN];
__device__ unsigned char     g_cls[BB * NN];
__device__ float  g_score [BB * TOPK];
__device__ float4 g_box   [BB * TOPK];   // un-offset xyxy
__device__ float4 g_boxoff[BB * TOPK];   // class-offset xyxy
__device__ float  g_clsf  [BB * TOPK];
__device__ unsigned long long g_mask[(size_t)BB * TOPK * 16]; // suppression bitmatrix
__device__ float  g_bmax[BB];
__device__ float  g_bwh [BB];
__device__ unsigned g_selcnt[BB];        // never reset: modulo trigger
__device__ unsigned g_ctr;               // never reset: modulo trigger

// =====================================================================
// Kernel 1 (fused): score 64 anchors per 1024-thr block; the block that
// finishes a batch (atomic modulo trigger) runs that batch's top-1024
// radix select + bitonic sort inline.
// key = sortable(score)<<32 | ~anchor  (desc value, asc index ties)
// =====================================================================
__global__ void __launch_bounds__(1024) prep_kernel(const float* __restrict__ in) {
    __shared__ __align__(16) unsigned char SM[41472];
    __shared__ int sT, sNW, sNB, sTrig;

    int tid = threadIdx.x, warp = tid >> 5, lane = tid & 31;
    int bid = blockIdx.x;
    int b = bid / BLKS_PER_B;
    int blk = bid % BLKS_PER_B;
    int base_anchor = blk * BLK_ANCH;
    int nanch = NN - base_anchor; if (nanch > BLK_ANCH) nanch = BLK_ANCH;

    // ---- phase A: stage + score ----
    {
        float* stage = (float*)SM;
        const float4* src = (const float4*)in + ((size_t)b * NN + base_anchor) * STRIDE / 4;
        float4* dst = (float4*)stage;
        int nfl4 = nanch * STRIDE / 4;       // 1360 or 1020
        for (int k = tid; k < nfl4; k += 1024) dst[k] = src[k];
        __syncthreads();

        #pragma unroll
        for (int a0 = 0; a0 < 2; a0++) {
            int a = warp + a0 * 32;
            if (a < nanch) {                         // warp-uniform
                const float* p = stage + a * STRIDE;
                float obj = p[4];                    // broadcast LDS
                float score = -1.0f;
                int cls = 0;
                if (obj > CONF_THRES) {              // warp-uniform
                    float v0 = p[lane];
                    float v1 = p[lane + 32];
                    float v2 = (lane < STRIDE - 64) ? p[lane + 64] : 0.0f;
                    float best = -1.0f; int bidx = 1 << 24;
                    if (lane >= 5) {
                        float pr = v0 * obj;
                        if (pr > best) { best = pr; bidx = lane - 5; }
                    }
                    {
                        float pr = v1 * obj; int ci = lane + 27;
                        if (pr > best) { best = pr; bidx = ci; }
                    }
                    if (lane < 21) {
                        float pr = v2 * obj; int ci = lane + 59;
                        if (pr > best) { best = pr; bidx = ci; }
                    }
                    unsigned mybits = __float_as_uint(best);      // >=0 products
                    unsigned vmax = __reduce_max_sync(0xffffffffu, mybits);
                    unsigned cand = (mybits == vmax) ? (unsigned)bidx : 0xFFFFFFFFu;
                    unsigned cmin = __reduce_min_sync(0xffffffffu, cand);
                    float conf = __uint_as_float(vmax);
                    cls = (int)cmin;
                    score = (conf > CONF_THRES) ? conf : -1.0f;
                }
                if (lane == 0) {
                    int anchor = base_anchor + a;
                    int gidx = b * NN + anchor;
                    unsigned u = __float_as_uint(score);
                    u = (u & 0x80000000u) ? ~u : (u | 0x80000000u);
                    g_keys[gidx] = ((unsigned long long)u << 32) | (unsigned)(~(unsigned)anchor);
                    g_cls[gidx] = (unsigned char)cls;
                }
            }
        }
    }

    // ---- trigger: last block of this batch proceeds to select ----
    __threadfence();
    __syncthreads();
    if (tid == 0) {
        unsigned old = atomicAdd(&g_selcnt[b], 1u);
        sTrig = (((old + 1u) % BLKS_PER_B) == 0u) ? 1 : 0;
    }
    __syncthreads();
    if (!sTrig) return;

    // ---- phase B: per-batch top-1024 select (smem reused) ----
    unsigned* hist = (unsigned*)SM;                                  // 16384 B
    unsigned long long* win = (unsigned long long*)(SM + 16384);     //  8192 B
    unsigned long long* bnd = (unsigned long long*)(SM + 24576);     // 16384 B
    unsigned* sWsum = (unsigned*)(SM + 40960);                       //   128 B

    const unsigned long long* keys = g_keys + (size_t)b * NN;

    for (int i = tid; i < 4096; i += 1024) hist[i] = 0;
    __syncthreads();
    for (int i = tid; i < NN; i += 1024) {
        unsigned bin = (unsigned)(__ldcg(&keys[i]) >> 52);
        atomicAdd(&hist[bin], 1u);
    }
    __syncthreads();

    unsigned cnt[4]; unsigned psum = 0;
    #pragma unroll
    for (int k = 0; k < 4; k++) { cnt[k] = hist[4095 - (4 * tid + k)]; psum += cnt[k]; }
    unsigned inc = psum;
    #pragma unroll
    for (int o = 1; o < 32; o <<= 1) {
        unsigned t = __shfl_up_sync(0xffffffffu, inc, o);
        if (lane >= o) inc += t;
    }
    if (lane == 31) sWsum[warp] = inc;
    __syncthreads();
    if (warp == 0) {
        unsigned wv = sWsum[lane];
        unsigned wi = wv;
        #pragma unroll
        for (int o = 1; o < 32; o <<= 1) {
            unsigned t = __shfl_up_sync(0xffffffffu, wi, o);
            if (lane >= o) wi += t;
        }
        sWsum[lane] = wi - wv;
    }
    __syncthreads();
    unsigned before = sWsum[warp] + inc - psum;

    unsigned c = before;
    #pragma unroll
    for (int k = 0; k < 4; k++) {
        unsigned h = cnt[k];
        if (c < TOPK && c + h >= TOPK) sT = 4095 - (4 * tid + k);
        c += h;
    }
    if (tid == 0) { sNW = 0; sNB = 0; }
    __syncthreads();

    int T = sT;
    for (int i = tid; i < NN; i += 1024) {
        unsigned long long k = __ldcg(&keys[i]);
        int bin = (int)(k >> 52);
        if (bin > T) { int pos = atomicAdd(&sNW, 1); win[pos] = k; }
        else if (bin == T) { int pos = atomicAdd(&sNB, 1); if (pos < BND_CAP) bnd[pos] = k; }
    }
    __syncthreads();
    int nB = sNB < BND_CAP ? sNB : BND_CAP;
    for (int i = tid; i < BND_CAP; i += 1024) if (i >= nB) bnd[i] = 0ULL;
    __syncthreads();

    for (int k = 2; k <= BND_CAP; k <<= 1) {
        for (int j = k >> 1; j > 0; j >>= 1) {
            #pragma unroll
            for (int h = 0; h < 2; h++) {
                int i = tid + h * 1024;
                int ixj = i ^ j;
                if (ixj > i) {
                    bool desc = ((i & k) == 0);
                    unsigned long long a = bnd[i], d = bnd[ixj];
                    bool sw = desc ? (a < d) : (a > d);
                    if (sw) { bnd[i] = d; bnd[ixj] = a; }
                }
            }
            __syncthreads();
        }
    }

    int nW = sNW;
    int need = TOPK - nW;
    for (int i = tid; i < need; i += 1024) win[nW + i] = bnd[i];
    __syncthreads();

    if (nW > 0) {
        for (int k = 2; k <= TOPK; k <<= 1) {
            for (int j = k >> 1; j > 0; j >>= 1) {
                int i = tid, ixj = i ^ j;
                if (ixj > i) {
                    bool desc = ((i & k) == 0);
                    unsigned long long a = win[i], d = win[ixj];
                    bool sw = desc ? (a < d) : (a > d);
                    if (sw) { win[i] = d; win[ixj] = a; }
                }
                __syncthreads();
            }
        }
    }

    {
        unsigned long long key = win[tid];
        unsigned u = (unsigned)(key >> 32);
        unsigned fb = (u & 0x80000000u) ? (u ^ 0x80000000u) : ~u;
        float score = __uint_as_float(fb);
        unsigned idx = ~((unsigned)(key & 0xffffffffu));

        const float* p = in + ((size_t)b * NN + idx) * STRIDE;
        float cx = p[0], cy = p[1], w = p[2], h = p[3];
        float x1 = cx - w * 0.5f, y1 = cy - h * 0.5f;
        float x2 = cx + w * 0.5f, y2 = cy + h * 0.5f;
        float cf = (float)__ldcg(&g_cls[(size_t)b * NN + idx]);
        float off = cf * MAX_WH;

        g_score [b * TOPK + tid] = score;
        g_box   [b * TOPK + tid] = make_float4(x1, y1, x2, y2);
        g_boxoff[b * TOPK + tid] = make_float4(x1 + off, y1 + off, x2 + off, y2 + off);
        g_clsf  [b * TOPK + tid] = cf;
    }
}

// =====================================================================
// Kernel 2: parallel suppression bitmatrix (upper triangle only).
// =====================================================================
__global__ void __launch_bounds__(256) iou_kernel() {
    int b = blockIdx.y;
    int tid = threadIdx.x, warp = tid >> 5, lane = tid & 31;
    __shared__ float4 cb[TOPK];
    for (int j = tid; j < TOPK; j += 256) cb[j] = g_boxoff[b * TOPK + j];
    __syncthreads();

    int i = blockIdx.x * 8 + warp;
    float4 bi = cb[i];
    float ai = (bi.z - bi.x) * (bi.w - bi.y);
    unsigned long long myw = 0;
    int s0 = i >> 5;
    #pragma unroll 4
    for (int s = s0; s < 32; s++) {
        int j = s * 32 + lane;
        float4 bj = cb[j];
        float lx = fmaxf(bi.x, bj.x);
        float ly = fmaxf(bi.y, bj.y);
        float rx = fminf(bi.z, bj.z);
        float ry = fminf(bi.w, bj.w);
        float iw = fmaxf(rx - lx, 0.0f);
        float ih = fmaxf(ry - ly, 0.0f);
        float inter = iw * ih;
        float aj = (bj.z - bj.x) * (bj.w - bj.y);
        float iou = inter / (ai + aj - inter + 1e-07f);
        bool pred = (j > i) && (iou > IOU_THR);
        unsigned bal = __ballot_sync(0xffffffffu, pred);
        if (lane == (s >> 1)) myw |= ((unsigned long long)bal) << ((s & 1) * 32);
    }
    if (lane < 16) g_mask[((size_t)b * TOPK + i) * 16 + lane] = myw;
}

// =====================================================================
// Kernel 3: 2-wide speculative greedy sweep (warp 0), full mask in
// 128KB dynamic smem, stats + det[2] + fused final reduction.
// =====================================================================
__global__ void __launch_bounds__(512) nms_kernel(float* __restrict__ out) {
    extern __shared__ unsigned long long sRows[];       // TOPK*16 words
    int b = blockIdx.x, tid = threadIdx.x, warp = tid >> 5, lane = tid & 31;
    __shared__ unsigned long long sRem[16];
    __shared__ int sKeptIdx[MAXDET + 1];
    __shared__ int sN;
    __shared__ float sRed[16];

    {
        const ulonglong2* srcv = (const ulonglong2*)(g_mask + (size_t)b * TOPK * 16);
        ulonglong2* dstv = (ulonglong2*)sRows;
        #pragma unroll
        for (int k = 0; k < 16; k++)
            dstv[tid + k * 512] = srcv[tid + k * 512];
    }

    {
        float s0 = g_score[b * TOPK + warp * 64 + lane];
        float s1 = g_score[b * TOPK + warp * 64 + 32 + lane];
        unsigned lo = __ballot_sync(0xffffffffu, s0 <= 0.0f);
        unsigned hi = __ballot_sync(0xffffffffu, s1 <= 0.0f);
        if (lane == 0) sRem[warp] = ((unsigned long long)hi << 32) | lo;
    }
    __syncthreads();

    if (warp == 0) {
        unsigned long long remw = (lane < 16) ? sRem[lane] : ~0ULL;
        int kept = 0;
        for (int w = 0; w < 16; w++) {
            unsigned long long alive = ~__shfl_sync(0xffffffffu, remw, w);
            while (alive) {
                unsigned long long a1 = alive & (alive - 1);
                int b1 = __ffsll((long long)alive) - 1;
                int i1 = (w << 6) + b1;
                int b2 = __ffsll((long long)a1) - 1;
                int b2s = (a1 != 0ULL) ? b2 : 0;
                int i2 = (w << 6) + b2s;
                // two parallel broadcast LDS
                unsigned long long r1 = sRows[i1 * 16 + w];
                unsigned long long r2 = sRows[i2 * 16 + w];
                bool keep2 = (a1 != 0ULL) && (((r1 >> b2s) & 1ULL) == 0ULL);
                // future-word accumulators (off-chain, lane-distributed)
                unsigned long long row1 = (lane < 16) ? sRows[i1 * 16 + lane] : 0ULL;
                unsigned long long row2 = (lane < 16) ? sRows[i2 * 16 + lane] : 0ULL;
                remw |= row1;
                if (keep2) remw |= row2;
                if (lane == 0) {
                    sKeptIdx[kept] = i1;
                    if (keep2) sKeptIdx[kept + 1] = i2;
                }
                kept += 1 + (int)keep2;
                if (kept >= MAXDET) goto sweep_done;
                unsigned long long t = a1 & ~r1;
                alive = keep2 ? ((t & (t - 1)) & ~r2) : t;
            }
        }
    sweep_done:
        if (lane == 0) sN = kept;
    }
    __syncthreads();
    int n = sN; if (n > MAXDET) n = MAXDET;

    float contrib = 0.0f;
    float4 bbx = make_float4(0, 0, 0, 0);
    float sc = 0.0f, cf = 0.0f;
    bool emit = (tid < n);
    if (emit) {
        int i = sKeptIdx[tid];
        sc = g_score[b * TOPK + i];
        bbx = g_box[b * TOPK + i];
        cf = g_clsf[b * TOPK + i];
        contrib = (fabsf(bbx.x - bbx.z) + fabsf(bbx.y - bbx.w)) * sc;
    }

    float v = contrib;
    #pragma unroll
    for (int o = 16; o > 0; o >>= 1) v += __shfl_down_sync(0xffffffffu, v, o);
    if (lane == 0) sRed[warp] = v;
    __syncthreads();
    if (tid == 0) {
        float x = 0.0f;
        #pragma unroll
        for (int k = 0; k < 16; k++) x += sRed[k];
        int mx = n > 1 ? n : 1;
        g_bwh[b]  = (n > 0) ? (x / (2.0f * (float)mx)) : 0.0f;
        g_bmax[b] = (n > 0) ? g_score[b * TOPK + sKeptIdx[0]] : 0.0f;
    }

    if (b == 2) {
        if (emit) {
            float* row = out + 2 + tid * 6;
            row[0] = bbx.x; row[1] = bbx.y; row[2] = bbx.z; row[3] = bbx.w;
            row[4] = sc; row[5] = cf;
        }
        if (tid >= n && tid < MAXDET) {
            float* row = out + 2 + tid * 6;
            #pragma unroll
            for (int k = 0; k < 6; k++) row[k] = 0.0f;
        }
    }

    __syncthreads();
    if (tid == 0) {
        __threadfence();
        unsigned old = atomicAdd(&g_ctr, 1u);
        if (((old + 1u) % BB) == 0u) {
            float m = 0.0f, w2 = 0.0f;
            #pragma unroll
            for (int k = 0; k < BB; k++) {
                m += __ldcg(&g_bmax[k]);
                w2 += __ldcg(&g_bwh[k]);
            }
            out[0] = m / (float)BB;
            out[1] = w2 / (float)BB;
        }
    }
}

extern "C" void kernel_launch(void* const* d_in, const int* in_sizes, int n_in,
                              void* d_out, int out_size) {
    const float* in = (const float*)d_in[0];
    float* out = (float*)d_out;

    static bool attr_done = false;
    if (!attr_done) {
        cudaFuncSetAttribute(nms_kernel,
                             cudaFuncAttributeMaxDynamicSharedMemorySize,
                             TOPK * 16 * (int)sizeof(unsigned long long));
        attr_done = true;
    }

    prep_kernel<<<BB * BLKS_PER_B, 1024>>>(in);        // 6304 blocks
    iou_kernel<<<dim3(TOPK / 8, BB), 256>>>();
    nms_kernel<<<BB, 512, TOPK * 16 * sizeof(unsigned long long)>>>(out);
}

// round 11
// speedup vs baseline: 1.1293x; 1.1293x over previous
#include <cuda_runtime.h>
#include <cstdint>

#define BB 16
#define NN 25200
#define NCLS 80
#define STRIDE 85
#define TOPK 1024
#define MAXDET 300
#define CONF_THRES 0.25f
#define IOU_THR 0.45f
#define MAX_WH 7680.0f
#define BND_CAP 2048
#define SBLK 128
#define SBLKS_PER_B 197     // ceil(25200/128)

// -------- scratch (device globals, no allocations) --------
__device__ unsigned long long g_keys[BB * NN];
__device__ float  g_score [BB * TOPK];
__device__ float4 g_box   [BB * TOPK];   // un-offset xyxy
__device__ float4 g_boxoff[BB * TOPK];   // class-offset xyxy
__device__ float  g_clsf  [BB * TOPK];
__device__ unsigned long long g_mask[(size_t)BB * TOPK * 16]; // suppression bitmatrix
__device__ float  g_bmax[BB];
__device__ float  g_bwh [BB];
__device__ unsigned g_ctr;               // never reset: modulo trigger

// =====================================================================
// Kernel A: 128-thr block stages 128 anchors via coalesced float4,
// then THREAD-per-anchor: conf = fl(max_c(raw cls) * obj) — bitwise
// equal to max_c(cls*obj) since obj>0 (fp mul monotone). No argmax
// here (deferred to select decode for the 1024 winners only).
// key = sortable(score)<<32 | ~anchor  (desc value, asc index ties)
// =====================================================================
__global__ void __launch_bounds__(SBLK) score_kernel(const float* __restrict__ in) {
    __shared__ float s[SBLK * STRIDE];   // 43520 B
    int tid = threadIdx.x;
    int bid = blockIdx.x;
    int b = bid / SBLKS_PER_B;
    int blk = bid % SBLKS_PER_B;
    int base = blk * SBLK;
    int nanch = NN - base; if (nanch > SBLK) nanch = SBLK;

    // stage: contiguous, 16B-aligned (base*85 divisible by 4)
    const float4* src = (const float4*)(in + ((size_t)b * NN + base) * STRIDE);
    float4* dst = (float4*)s;
    int nf4 = nanch * STRIDE / 4;        // nanch even -> exact
    for (int k = tid; k < nf4; k += SBLK) dst[k] = src[k];
    __syncthreads();

    if (tid < nanch) {
        int rb = tid * STRIDE;
        float obj = s[rb + 4];
        float conf = -1.0f;
        if (obj > CONF_THRES) {
            float m = 0.0f;                          // raw cls values are >= 0
            int first = rb + 5, last = rb + STRIDE;
            int a4 = (first + 3) & ~3;
            int k4end = last & ~3;
            for (int i = first; i < a4; i++) m = fmaxf(m, s[i]);
            for (int k = a4; k < k4end; k += 4) {
                float4 v = *(const float4*)(s + k);
                m = fmaxf(m, v.x); m = fmaxf(m, v.y);
                m = fmaxf(m, v.z); m = fmaxf(m, v.w);
            }
            for (int i = k4end; i < last; i++) m = fmaxf(m, s[i]);
            float c = m * obj;                       // == max(cls*obj) bitwise
            conf = (c > CONF_THRES) ? c : -1.0f;
        }
        unsigned u = __float_as_uint(conf);
        u = (u & 0x80000000u) ? ~u : (u | 0x80000000u);
        unsigned anchor = (unsigned)(base + tid);
        g_keys[(size_t)b * NN + anchor] =
            ((unsigned long long)u << 32) | (unsigned)(~anchor);
    }
}

// =====================================================================
// Kernel B: per-batch exact sorted top-1024 via 12-bit radix select +
// bitonic sorts. 1 block (1024 thr) per batch. Decode recomputes the
// exact product-argmax (first-index ties) for the 1024 winners.
// =====================================================================
__global__ void __launch_bounds__(1024) select_kernel(const float* __restrict__ in) {
    int b = blockIdx.x;
    int tid = threadIdx.x;
    int warp = tid >> 5, lane = tid & 31;

    __shared__ unsigned hist[4096];
    __shared__ unsigned sWsum[32];
    __shared__ unsigned long long win[TOPK];
    __shared__ unsigned long long bnd[BND_CAP];
    __shared__ int sT, sNW, sNB;

    const unsigned long long* keys = g_keys + (size_t)b * NN;

    for (int i = tid; i < 4096; i += 1024) hist[i] = 0;
    __syncthreads();
    for (int i = tid; i < NN; i += 1024) {
        unsigned bin = (unsigned)(keys[i] >> 52);
        atomicAdd(&hist[bin], 1u);
    }
    __syncthreads();

    unsigned cnt[4]; unsigned psum = 0;
    #pragma unroll
    for (int k = 0; k < 4; k++) { cnt[k] = hist[4095 - (4 * tid + k)]; psum += cnt[k]; }
    unsigned inc = psum;
    #pragma unroll
    for (int o = 1; o < 32; o <<= 1) {
        unsigned t = __shfl_up_sync(0xffffffffu, inc, o);
        if (lane >= o) inc += t;
    }
    if (lane == 31) sWsum[warp] = inc;
    __syncthreads();
    if (warp == 0) {
        unsigned wv = sWsum[lane];
        unsigned wi = wv;
        #pragma unroll
        for (int o = 1; o < 32; o <<= 1) {
            unsigned t = __shfl_up_sync(0xffffffffu, wi, o);
            if (lane >= o) wi += t;
        }
        sWsum[lane] = wi - wv;
    }
    __syncthreads();
    unsigned before = sWsum[warp] + inc - psum;

    unsigned c = before;
    #pragma unroll
    for (int k = 0; k < 4; k++) {
        unsigned h = cnt[k];
        if (c < TOPK && c + h >= TOPK) sT = 4095 - (4 * tid + k);
        c += h;
    }
    if (tid == 0) { sNW = 0; sNB = 0; }
    __syncthreads();

    int T = sT;
    for (int i = tid; i < NN; i += 1024) {
        unsigned long long k = keys[i];
        int bin = (int)(k >> 52);
        if (bin > T) { int pos = atomicAdd(&sNW, 1); win[pos] = k; }
        else if (bin == T) { int pos = atomicAdd(&sNB, 1); if (pos < BND_CAP) bnd[pos] = k; }
    }
    __syncthreads();
    int nB = sNB < BND_CAP ? sNB : BND_CAP;
    for (int i = tid; i < BND_CAP; i += 1024) if (i >= nB) bnd[i] = 0ULL;
    __syncthreads();

    for (int k = 2; k <= BND_CAP; k <<= 1) {
        for (int j = k >> 1; j > 0; j >>= 1) {
            #pragma unroll
            for (int h = 0; h < 2; h++) {
                int i = tid + h * 1024;
                int ixj = i ^ j;
                if (ixj > i) {
                    bool desc = ((i & k) == 0);
                    unsigned long long a = bnd[i], d = bnd[ixj];
                    bool sw = desc ? (a < d) : (a > d);
                    if (sw) { bnd[i] = d; bnd[ixj] = a; }
                }
            }
            __syncthreads();
        }
    }

    int nW = sNW;
    int need = TOPK - nW;
    for (int i = tid; i < need; i += 1024) win[nW + i] = bnd[i];
    __syncthreads();

    if (nW > 0) {
        for (int k = 2; k <= TOPK; k <<= 1) {
            for (int j = k >> 1; j > 0; j >>= 1) {
                int i = tid, ixj = i ^ j;
                if (ixj > i) {
                    bool desc = ((i & k) == 0);
                    unsigned long long a = win[i], d = win[ixj];
                    bool sw = desc ? (a < d) : (a > d);
                    if (sw) { win[i] = d; win[ixj] = a; }
                }
                __syncthreads();
            }
        }
    }

    // decode + exact product-argmax for winners only
    {
        unsigned long long key = win[tid];
        unsigned u = (unsigned)(key >> 32);
        unsigned fb = (u & 0x80000000u) ? (u ^ 0x80000000u) : ~u;
        float score = __uint_as_float(fb);
        unsigned idx = ~((unsigned)(key & 0xffffffffu));

        const float* p = in + ((size_t)b * NN + idx) * STRIDE;
        float cx = p[0], cy = p[1], w = p[2], h = p[3];
        float obj = p[4];
        float x1 = cx - w * 0.5f, y1 = cy - h * 0.5f;
        float x2 = cx + w * 0.5f, y2 = cy + h * 0.5f;

        float best = -1.0f; int cls = 0;
        #pragma unroll 4
        for (int j = 0; j < NCLS; j++) {
            float pr = p[5 + j] * obj;               // exact reference order
            if (pr > best) { best = pr; cls = j; }   // first-index ties
        }
        float cf = (float)cls;
        float off = cf * MAX_WH;

        g_score [b * TOPK + tid] = score;
        g_box   [b * TOPK + tid] = make_float4(x1, y1, x2, y2);
        g_boxoff[b * TOPK + tid] = make_float4(x1 + off, y1 + off, x2 + off, y2 + off);
        g_clsf  [b * TOPK + tid] = cf;
    }
}

// =====================================================================
// Kernel C1: parallel suppression bitmatrix (upper triangle only).
// =====================================================================
__global__ void __launch_bounds__(256) iou_kernel() {
    int b = blockIdx.y;
    int tid = threadIdx.x, warp = tid >> 5, lane = tid & 31;
    __shared__ float4 cb[TOPK];
    for (int j = tid; j < TOPK; j += 256) cb[j] = g_boxoff[b * TOPK + j];
    __syncthreads();

    int i = blockIdx.x * 8 + warp;
    float4 bi = cb[i];
    float ai = (bi.z - bi.x) * (bi.w - bi.y);
    unsigned long long myw = 0;
    int s0 = i >> 5;
    #pragma unroll 4
    for (int s = s0; s < 32; s++) {
        int j = s * 32 + lane;
        float4 bj = cb[j];
        float lx = fmaxf(bi.x, bj.x);
        float ly = fmaxf(bi.y, bj.y);
        float rx = fminf(bi.z, bj.z);
        float ry = fminf(bi.w, bj.w);
        float iw = fmaxf(rx - lx, 0.0f);
        float ih = fmaxf(ry - ly, 0.0f);
        float inter = iw * ih;
        float aj = (bj.z - bj.x) * (bj.w - bj.y);
        float iou = inter / (ai + aj - inter + 1e-07f);
        bool pred = (j > i) && (iou > IOU_THR);
        unsigned bal = __ballot_sync(0xffffffffu, pred);
        if (lane == (s >> 1)) myw |= ((unsigned long long)bal) << ((s & 1) * 32);
    }
    if (lane < 16) g_mask[((size_t)b * TOPK + i) * 16 + lane] = myw;
}

// =====================================================================
// Kernel C2: 2-wide speculative greedy sweep (warp 0), full mask in
// 128KB dynamic smem, stats + det[2] + fused final reduction.
// =====================================================================
__global__ void __launch_bounds__(512) nms_kernel(float* __restrict__ out) {
    extern __shared__ unsigned long long sRows[];       // TOPK*16 words
    int b = blockIdx.x, tid = threadIdx.x, warp = tid >> 5, lane = tid & 31;
    __shared__ unsigned long long sRem[16];
    __shared__ int sKeptIdx[MAXDET + 1];
    __shared__ int sN;
    __shared__ float sRed[16];

    {
        const ulonglong2* srcv = (const ulonglong2*)(g_mask + (size_t)b * TOPK * 16);
        ulonglong2* dstv = (ulonglong2*)sRows;
        #pragma unroll
        for (int k = 0; k < 16; k++)
            dstv[tid + k * 512] = srcv[tid + k * 512];
    }

    {
        float s0 = g_score[b * TOPK + warp * 64 + lane];
        float s1 = g_score[b * TOPK + warp * 64 + 32 + lane];
        unsigned lo = __ballot_sync(0xffffffffu, s0 <= 0.0f);
        unsigned hi = __ballot_sync(0xffffffffu, s1 <= 0.0f);
        if (lane == 0) sRem[warp] = ((unsigned long long)hi << 32) | lo;
    }
    __syncthreads();

    if (warp == 0) {
        unsigned long long remw = (lane < 16) ? sRem[lane] : ~0ULL;
        int kept = 0;
        for (int w = 0; w < 16; w++) {
            unsigned long long alive = ~__shfl_sync(0xffffffffu, remw, w);
            while (alive) {
                unsigned long long a1 = alive & (alive - 1);
                int b1 = __ffsll((long long)alive) - 1;
                int i1 = (w << 6) + b1;
                int b2 = __ffsll((long long)a1) - 1;
                int b2s = (a1 != 0ULL) ? b2 : 0;
                int i2 = (w << 6) + b2s;
                unsigned long long r1 = sRows[i1 * 16 + w];
                unsigned long long r2 = sRows[i2 * 16 + w];
                bool keep2 = (a1 != 0ULL) && (((r1 >> b2s) & 1ULL) == 0ULL);
                unsigned long long row1 = (lane < 16) ? sRows[i1 * 16 + lane] : 0ULL;
                unsigned long long row2 = (lane < 16) ? sRows[i2 * 16 + lane] : 0ULL;
                remw |= row1;
                if (keep2) remw |= row2;
                if (lane == 0) {
                    sKeptIdx[kept] = i1;
                    if (keep2) sKeptIdx[kept + 1] = i2;
                }
                kept += 1 + (int)keep2;
                if (kept >= MAXDET) goto sweep_done;
                unsigned long long t = a1 & ~r1;
                alive = keep2 ? ((t & (t - 1)) & ~r2) : t;
            }
        }
    sweep_done:
        if (lane == 0) sN = kept;
    }
    __syncthreads();
    int n = sN; if (n > MAXDET) n = MAXDET;

    float contrib = 0.0f;
    float4 bbx = make_float4(0, 0, 0, 0);
    float sc = 0.0f, cf = 0.0f;
    bool emit = (tid < n);
    if (emit) {
        int i = sKeptIdx[tid];
        sc = g_score[b * TOPK + i];
        bbx = g_box[b * TOPK + i];
        cf = g_clsf[b * TOPK + i];
        contrib = (fabsf(bbx.x - bbx.z) + fabsf(bbx.y - bbx.w)) * sc;
    }

    float v = contrib;
    #pragma unroll
    for (int o = 16; o > 0; o >>= 1) v += __shfl_down_sync(0xffffffffu, v, o);
    if (lane == 0) sRed[warp] = v;
    __syncthreads();
    if (tid == 0) {
        float x = 0.0f;
        #pragma unroll
        for (int k = 0; k < 16; k++) x += sRed[k];
        int mx = n > 1 ? n : 1;
        g_bwh[b]  = (n > 0) ? (x / (2.0f * (float)mx)) : 0.0f;
        g_bmax[b] = (n > 0) ? g_score[b * TOPK + sKeptIdx[0]] : 0.0f;
    }

    if (b == 2) {
        if (emit) {
            float* row = out + 2 + tid * 6;
            row[0] = bbx.x; row[1] = bbx.y; row[2] = bbx.z; row[3] = bbx.w;
            row[4] = sc; row[5] = cf;
        }
        if (tid >= n && tid < MAXDET) {
            float* row = out + 2 + tid * 6;
            #pragma unroll
            for (int k = 0; k < 6; k++) row[k] = 0.0f;
        }
    }

    __syncthreads();
    if (tid == 0) {
        __threadfence();
        unsigned old = atomicAdd(&g_ctr, 1u);
        if (((old + 1u) % BB) == 0u) {
            float m = 0.0f, w2 = 0.0f;
            #pragma unroll
            for (int k = 0; k < BB; k++) {
                m += __ldcg(&g_bmax[k]);
                w2 += __ldcg(&g_bwh[k]);
            }
            out[0] = m / (float)BB;
            out[1] = w2 / (float)BB;
        }
    }
}

extern "C" void kernel_launch(void* const* d_in, const int* in_sizes, int n_in,
                              void* d_out, int out_size) {
    const float* in = (const float*)d_in[0];
    float* out = (float*)d_out;

    static bool attr_done = false;
    if (!attr_done) {
        cudaFuncSetAttribute(nms_kernel,
                             cudaFuncAttributeMaxDynamicSharedMemorySize,
                             TOPK * 16 * (int)sizeof(unsigned long long));
        attr_done = true;
    }

    score_kernel<<<BB * SBLKS_PER_B, SBLK>>>(in);      // 3152 blocks
    select_kernel<<<BB, 1024>>>(in);
    iou_kernel<<<dim3(TOPK / 8, BB), 256>>>();
    nms_kernel<<<BB, 512, TOPK * 16 * sizeof(unsigned long long)>>>(out);
}

// round 12
// speedup vs baseline: 1.1966x; 1.0596x over previous
#include <cuda_runtime.h>
#include <cstdint>

#define BB 16
#define NN 25200
#define NCLS 80
#define STRIDE 85
#define TOPK 1024
#define MAXDET 300
#define CONF_THRES 0.25f
#define IOU_THR 0.45f
#define MAX_WH 7680.0f
#define BND_CAP 2048

// -------- scratch (device globals, no allocations) --------
__device__ unsigned long long g_keys[BB * NN];
__device__ float  g_score [BB * TOPK];
__device__ float4 g_box   [BB * TOPK];   // un-offset xyxy
__device__ float4 g_boxoff[BB * TOPK];   // class-offset xyxy
__device__ float  g_clsf  [BB * TOPK];
__device__ unsigned long long g_mask[(size_t)BB * TOPK * 16]; // suppression bitmatrix
__device__ float  g_bmax[BB];
__device__ float  g_bwh [BB];
__device__ unsigned g_ctr;               // never reset: modulo trigger

// =====================================================================
// Kernel A: block of 256 stages 16 anchors (5440B) via aligned float4,
// then warp-per-anchor. conf = fl(max_c(raw cls) * obj) — bitwise equal
// to max_c(cls*obj) since cls>=0 and fp mul by obj>0 is monotone.
// No argmax here (deferred to select decode for winners only).
// key = sortable(score)<<32 | ~anchor  (desc value, asc index ties)
// =====================================================================
__global__ void __launch_bounds__(256) score_kernel(const float* __restrict__ in) {
    __shared__ float s[16 * STRIDE];   // 1360 floats
    int group = blockIdx.x;
    int tid = threadIdx.x;

    const float4* src = (const float4*)in + (size_t)group * 340;
    float4* dst = (float4*)s;
    {
        int k0 = tid, k1 = tid + 256;
        dst[k0] = src[k0];
        if (k1 < 340) dst[k1] = src[k1];
    }
    __syncthreads();

    int warp = tid >> 5, lane = tid & 31;
    #pragma unroll
    for (int a0 = 0; a0 < 2; a0++) {
        int a = warp + a0 * 8;
        const float* p = s + a * STRIDE;
        float obj = p[4];                       // broadcast LDS (uniform addr)

        float score = -1.0f;
        if (obj > CONF_THRES) {                 // warp-uniform branch
            // raw class max (values >= 0), elements 5..84
            float m = 0.0f;
            if (lane >= 5) m = p[lane];                 // e = lane
            m = fmaxf(m, p[lane + 32]);                 // e = lane+32
            if (lane < 21) m = fmaxf(m, p[lane + 64]);  // e = lane+64
            // >=0 floats: integer order == float order
            unsigned vmax = __reduce_max_sync(0xffffffffu, __float_as_uint(m));
            float c = __uint_as_float(vmax) * obj;      // == max(cls*obj) bitwise
            score = (c > CONF_THRES) ? c : -1.0f;
        }
        if (lane == 0) {
            int gidx = group * 16 + a;
            unsigned u = __float_as_uint(score);
            u = (u & 0x80000000u) ? ~u : (u | 0x80000000u);
            unsigned anchor = (unsigned)(gidx % NN);
            g_keys[gidx] = ((unsigned long long)u << 32) | (unsigned)(~anchor);
        }
    }
}

// =====================================================================
// Kernel B: per-batch exact sorted top-1024 via 12-bit radix select +
// bitonic sorts. 1 block (1024 thr) per batch. Decode recomputes the
// exact product-argmax (first-index ties) for the 1024 winners.
// =====================================================================
__global__ void __launch_bounds__(1024) select_kernel(const float* __restrict__ in) {
    int b = blockIdx.x;
    int tid = threadIdx.x;
    int warp = tid >> 5, lane = tid & 31;

    __shared__ unsigned hist[4096];
    __shared__ unsigned sWsum[32];
    __shared__ unsigned long long win[TOPK];
    __shared__ unsigned long long bnd[BND_CAP];
    __shared__ int sT, sNW, sNB;

    const unsigned long long* keys = g_keys + (size_t)b * NN;

    for (int i = tid; i < 4096; i += 1024) hist[i] = 0;
    __syncthreads();
    for (int i = tid; i < NN; i += 1024) {
        unsigned bin = (unsigned)(keys[i] >> 52);
        atomicAdd(&hist[bin], 1u);
    }
    __syncthreads();

    unsigned cnt[4]; unsigned psum = 0;
    #pragma unroll
    for (int k = 0; k < 4; k++) { cnt[k] = hist[4095 - (4 * tid + k)]; psum += cnt[k]; }
    unsigned inc = psum;
    #pragma unroll
    for (int o = 1; o < 32; o <<= 1) {
        unsigned t = __shfl_up_sync(0xffffffffu, inc, o);
        if (lane >= o) inc += t;
    }
    if (lane == 31) sWsum[warp] = inc;
    __syncthreads();
    if (warp == 0) {
        unsigned wv = sWsum[lane];
        unsigned wi = wv;
        #pragma unroll
        for (int o = 1; o < 32; o <<= 1) {
            unsigned t = __shfl_up_sync(0xffffffffu, wi, o);
            if (lane >= o) wi += t;
        }
        sWsum[lane] = wi - wv;
    }
    __syncthreads();
    unsigned before = sWsum[warp] + inc - psum;

    unsigned c = before;
    #pragma unroll
    for (int k = 0; k < 4; k++) {
        unsigned h = cnt[k];
        if (c < TOPK && c + h >= TOPK) sT = 4095 - (4 * tid + k);
        c += h;
    }
    if (tid == 0) { sNW = 0; sNB = 0; }
    __syncthreads();

    int T = sT;
    for (int i = tid; i < NN; i += 1024) {
        unsigned long long k = keys[i];
        int bin = (int)(k >> 52);
        if (bin > T) { int pos = atomicAdd(&sNW, 1); win[pos] = k; }
        else if (bin == T) { int pos = atomicAdd(&sNB, 1); if (pos < BND_CAP) bnd[pos] = k; }
    }
    __syncthreads();
    int nB = sNB < BND_CAP ? sNB : BND_CAP;
    for (int i = tid; i < BND_CAP; i += 1024) if (i >= nB) bnd[i] = 0ULL;
    __syncthreads();

    for (int k = 2; k <= BND_CAP; k <<= 1) {
        for (int j = k >> 1; j > 0; j >>= 1) {
            #pragma unroll
            for (int h = 0; h < 2; h++) {
                int i = tid + h * 1024;
                int ixj = i ^ j;
                if (ixj > i) {
                    bool desc = ((i & k) == 0);
                    unsigned long long a = bnd[i], d = bnd[ixj];
                    bool sw = desc ? (a < d) : (a > d);
                    if (sw) { bnd[i] = d; bnd[ixj] = a; }
                }
            }
            __syncthreads();
        }
    }

    int nW = sNW;
    int need = TOPK - nW;
    for (int i = tid; i < need; i += 1024) win[nW + i] = bnd[i];
    __syncthreads();

    if (nW > 0) {
        for (int k = 2; k <= TOPK; k <<= 1) {
            for (int j = k >> 1; j > 0; j >>= 1) {
                int i = tid, ixj = i ^ j;
                if (ixj > i) {
                    bool desc = ((i & k) == 0);
                    unsigned long long a = win[i], d = win[ixj];
                    bool sw = desc ? (a < d) : (a > d);
                    if (sw) { win[i] = d; win[ixj] = a; }
                }
                __syncthreads();
            }
        }
    }

    // decode + exact product-argmax for winners only
    {
        unsigned long long key = win[tid];
        unsigned u = (unsigned)(key >> 32);
        unsigned fb = (u & 0x80000000u) ? (u ^ 0x80000000u) : ~u;
        float score = __uint_as_float(fb);
        unsigned idx = ~((unsigned)(key & 0xffffffffu));

        const float* p = in + ((size_t)b * NN + idx) * STRIDE;
        float cx = p[0], cy = p[1], w = p[2], h = p[3];
        float obj = p[4];
        float x1 = cx - w * 0.5f, y1 = cy - h * 0.5f;
        float x2 = cx + w * 0.5f, y2 = cy + h * 0.5f;

        float best = -1.0f; int cls = 0;
        #pragma unroll 4
        for (int j = 0; j < NCLS; j++) {
            float pr = p[5 + j] * obj;               // exact reference order
            if (pr > best) { best = pr; cls = j; }   // first-index ties
        }
        float cf = (float)cls;
        float off = cf * MAX_WH;

        g_score [b * TOPK + tid] = score;
        g_box   [b * TOPK + tid] = make_float4(x1, y1, x2, y2);
        g_boxoff[b * TOPK + tid] = make_float4(x1 + off, y1 + off, x2 + off, y2 + off);
        g_clsf  [b * TOPK + tid] = cf;
    }
}

// =====================================================================
// Kernel C1: parallel suppression bitmatrix (upper triangle only).
// =====================================================================
__global__ void __launch_bounds__(256) iou_kernel() {
    int b = blockIdx.y;
    int tid = threadIdx.x, warp = tid >> 5, lane = tid & 31;
    __shared__ float4 cb[TOPK];
    for (int j = tid; j < TOPK; j += 256) cb[j] = g_boxoff[b * TOPK + j];
    __syncthreads();

    int i = blockIdx.x * 8 + warp;
    float4 bi = cb[i];
    float ai = (bi.z - bi.x) * (bi.w - bi.y);
    unsigned long long myw = 0;
    int s0 = i >> 5;
    #pragma unroll 4
    for (int s = s0; s < 32; s++) {
        int j = s * 32 + lane;
        float4 bj = cb[j];
        float lx = fmaxf(bi.x, bj.x);
        float ly = fmaxf(bi.y, bj.y);
        float rx = fminf(bi.z, bj.z);
        float ry = fminf(bi.w, bj.w);
        float iw = fmaxf(rx - lx, 0.0f);
        float ih = fmaxf(ry - ly, 0.0f);
        float inter = iw * ih;
        float aj = (bj.z - bj.x) * (bj.w - bj.y);
        float iou = inter / (ai + aj - inter + 1e-07f);
        bool pred = (j > i) && (iou > IOU_THR);
        unsigned bal = __ballot_sync(0xffffffffu, pred);
        if (lane == (s >> 1)) myw |= ((unsigned long long)bal) << ((s & 1) * 32);
    }
    if (lane < 16) g_mask[((size_t)b * TOPK + i) * 16 + lane] = myw;
}

// =====================================================================
// Kernel C2: word-major branch-lean greedy sweep (warp 0), full mask
// in 128KB dynamic smem, stats + det[2] + fused final reduction.
// =====================================================================
__global__ void __launch_bounds__(512) nms_kernel(float* __restrict__ out) {
    extern __shared__ unsigned long long sRows[];       // TOPK*16 words
    int b = blockIdx.x, tid = threadIdx.x, warp = tid >> 5, lane = tid & 31;
    __shared__ unsigned long long sRem[16];
    __shared__ int sKeptIdx[MAXDET];
    __shared__ int sN;
    __shared__ float sRed[16];

    {
        const ulonglong2* srcv = (const ulonglong2*)(g_mask + (size_t)b * TOPK * 16);
        ulonglong2* dstv = (ulonglong2*)sRows;
        #pragma unroll
        for (int k = 0; k < 16; k++)
            dstv[tid + k * 512] = srcv[tid + k * 512];
    }

    {
        float s0 = g_score[b * TOPK + warp * 64 + lane];
        float s1 = g_score[b * TOPK + warp * 64 + 32 + lane];
        unsigned lo = __ballot_sync(0xffffffffu, s0 <= 0.0f);
        unsigned hi = __ballot_sync(0xffffffffu, s1 <= 0.0f);
        if (lane == 0) sRem[warp] = ((unsigned long long)hi << 32) | lo;
    }
    __syncthreads();

    if (warp == 0) {
        unsigned long long remw = (lane < 16) ? sRem[lane] : ~0ULL;
        int kept = 0;
        for (int w = 0; w < 16; w++) {
            unsigned long long alive = ~__shfl_sync(0xffffffffu, remw, w);
            while (alive) {
                int bit = __ffsll((long long)alive) - 1;
                int i = (w << 6) + bit;
                if (lane == 0) sKeptIdx[kept] = i;     // predicated STS
                kept++;
                if (kept >= MAXDET) goto sweep_done;   // rare forward branch
                unsigned long long rcur = sRows[i * 16 + w];          // broadcast
                unsigned long long rown = (lane < 16) ? sRows[i * 16 + lane] : 0ULL;
                remw |= rown;                           // off-chain
                alive = (alive & (alive - 1)) & ~rcur;  // chain
            }
        }
    sweep_done:
        if (lane == 0) sN = kept;
    }
    __syncthreads();
    int n = sN;

    float contrib = 0.0f;
    float4 bbx = make_float4(0, 0, 0, 0);
    float sc = 0.0f, cf = 0.0f;
    bool emit = (tid < n);
    if (emit) {
        int i = sKeptIdx[tid];
        sc = g_score[b * TOPK + i];
        bbx = g_box[b * TOPK + i];
        cf = g_clsf[b * TOPK + i];
        contrib = (fabsf(bbx.x - bbx.z) + fabsf(bbx.y - bbx.w)) * sc;
    }

    float v = contrib;
    #pragma unroll
    for (int o = 16; o > 0; o >>= 1) v += __shfl_down_sync(0xffffffffu, v, o);
    if (lane == 0) sRed[warp] = v;
    __syncthreads();
    if (tid == 0) {
        float x = 0.0f;
        #pragma unroll
        for (int k = 0; k < 16; k++) x += sRed[k];
        int mx = n > 1 ? n : 1;
        g_bwh[b]  = (n > 0) ? (x / (2.0f * (float)mx)) : 0.0f;
        g_bmax[b] = (n > 0) ? g_score[b * TOPK + sKeptIdx[0]] : 0.0f;
    }

    if (b == 2) {
        if (emit) {
            float* row = out + 2 + tid * 6;
            row[0] = bbx.x; row[1] = bbx.y; row[2] = bbx.z; row[3] = bbx.w;
            row[4] = sc; row[5] = cf;
        }
        if (tid >= n && tid < MAXDET) {
            float* row = out + 2 + tid * 6;
            #pragma unroll
            for (int k = 0; k < 6; k++) row[k] = 0.0f;
        }
    }

    __syncthreads();
    if (tid == 0) {
        __threadfence();
        unsigned old = atomicAdd(&g_ctr, 1u);
        if (((old + 1u) % BB) == 0u) {
            float m = 0.0f, w2 = 0.0f;
            #pragma unroll
            for (int k = 0; k < BB; k++) {
                m += __ldcg(&g_bmax[k]);
                w2 += __ldcg(&g_bwh[k]);
            }
            out[0] = m / (float)BB;
            out[1] = w2 / (float)BB;
        }
    }
}

extern "C" void kernel_launch(void* const* d_in, const int* in_sizes, int n_in,
                              void* d_out, int out_size) {
    const float* in = (const float*)d_in[0];
    float* out = (float*)d_out;

    static bool attr_done = false;
    if (!attr_done) {
        cudaFuncSetAttribute(nms_kernel,
                             cudaFuncAttributeMaxDynamicSharedMemorySize,
                             TOPK * 16 * (int)sizeof(unsigned long long));
        attr_done = true;
    }

    score_kernel<<<BB * NN / 16, 256>>>(in);   // 25200 blocks
    select_kernel<<<BB, 1024>>>(in);
    iou_kernel<<<dim3(TOPK / 8, BB), 256>>>();
    nms_kernel<<<BB, 512, TOPK * 16 * sizeof(unsigned long long)>>>(out);
}

// round 13
// speedup vs baseline: 1.3164x; 1.1001x over previous
#include <cuda_runtime.h>
#include <cstdint>

#define BB 16
#define NN 25200
#define NCLS 80
#define STRIDE 85
#define TOPK 1024
#define MAXDET 300
#define CONF_THRES 0.25f
#define IOU_THR 0.45f
#define MAX_WH 7680.0f
#define BND_CAP 2048
#define PASSES 4            // anchors per warp per block

// -------- scratch (device globals, no allocations) --------
__device__ unsigned long long g_keys[BB * NN];
__device__ unsigned char     g_cls[BB * NN];
__device__ float  g_score [BB * TOPK];
__device__ float4 g_box   [BB * TOPK];   // un-offset xyxy
__device__ float4 g_boxoff[BB * TOPK];   // class-offset xyxy
__device__ float  g_clsf  [BB * TOPK];
__device__ unsigned long long g_mask[(size_t)BB * TOPK * 16]; // suppression bitmatrix
__device__ float  g_bmax[BB];
__device__ float  g_bwh [BB];
__device__ unsigned g_ctr;               // never reset: modulo trigger

// =====================================================================
// Kernel A: warp-per-anchor DIRECT from global (no smem staging).
// Lane-consecutive LDG.32 -> coalesced. Exact reference product-argmax
// via REDUX pair. 4 anchors per warp (unrolled) for load MLP.
// key = sortable(score)<<32 | ~anchor  (desc value, asc index ties)
// =====================================================================
__global__ void __launch_bounds__(256) score_kernel(const float* __restrict__ in) {
    int tid = threadIdx.x, warp = tid >> 5, lane = tid & 31;
    int base = blockIdx.x * (8 * PASSES);     // 8 warps/block

    #pragma unroll
    for (int pass = 0; pass < PASSES; pass++) {
        int gidx = base + pass * 8 + warp;    // < BB*NN always (exact grid)
        const float* p = in + (size_t)gidx * STRIDE;

        float v0 = p[lane];
        float v1 = p[lane + 32];
        float v2 = (lane < STRIDE - 64) ? p[lane + 64] : 0.0f;
        float obj = __shfl_sync(0xffffffffu, v0, 4);

        float score = -1.0f;
        int cls = 0;
        if (obj > CONF_THRES) {               // warp-uniform branch
            float best = -1.0f; int bidx = 1 << 24;
            if (lane >= 5) {
                float pr = v0 * obj;
                if (pr > best) { best = pr; bidx = lane - 5; }
            }
            {
                float pr = v1 * obj; int ci = lane + 27;
                if (pr > best) { best = pr; bidx = ci; }
            }
            if (lane < 21) {
                float pr = v2 * obj; int ci = lane + 59;
                if (pr > best) { best = pr; bidx = ci; }
            }
            // all candidate products >= 0: integer order == float order
            unsigned mybits = __float_as_uint(best < 0.0f ? 0.0f : best);
            // (lanes 0-4 before v1 step cannot stay -1: v1 product always set)
            mybits = __float_as_uint(best);
            unsigned vmax = __reduce_max_sync(0xffffffffu, mybits);
            unsigned cand = (mybits == vmax) ? (unsigned)bidx : 0xFFFFFFFFu;
            unsigned cmin = __reduce_min_sync(0xffffffffu, cand);
            float conf = __uint_as_float(vmax);
            cls = (int)cmin;
            score = (conf > CONF_THRES) ? conf : -1.0f;
        }
        if (lane == 0) {
            unsigned u = __float_as_uint(score);
            u = (u & 0x80000000u) ? ~u : (u | 0x80000000u);
            unsigned anchor = (unsigned)(gidx % NN);
            g_keys[gidx] = ((unsigned long long)u << 32) | (unsigned)(~anchor);
            g_cls[gidx] = (unsigned char)cls;
        }
    }
}

// =====================================================================
// Kernel B: per-batch exact sorted top-1024 via 12-bit radix select +
// bitonic sorts. 1 block (1024 thr) per batch. Warp-shuffle scan.
// Decode reads g_cls (computed exactly in score).
// =====================================================================
__global__ void __launch_bounds__(1024) select_kernel(const float* __restrict__ in) {
    int b = blockIdx.x;
    int tid = threadIdx.x;
    int warp = tid >> 5, lane = tid & 31;

    __shared__ unsigned hist[4096];
    __shared__ unsigned sWsum[32];
    __shared__ unsigned long long win[TOPK];
    __shared__ unsigned long long bnd[BND_CAP];
    __shared__ int sT, sNW, sNB;

    const unsigned long long* keys = g_keys + (size_t)b * NN;

    for (int i = tid; i < 4096; i += 1024) hist[i] = 0;
    __syncthreads();
    for (int i = tid; i < NN; i += 1024) {
        unsigned bin = (unsigned)(keys[i] >> 52);
        atomicAdd(&hist[bin], 1u);
    }
    __syncthreads();

    unsigned cnt[4]; unsigned psum = 0;
    #pragma unroll
    for (int k = 0; k < 4; k++) { cnt[k] = hist[4095 - (4 * tid + k)]; psum += cnt[k]; }
    unsigned inc = psum;
    #pragma unroll
    for (int o = 1; o < 32; o <<= 1) {
        unsigned t = __shfl_up_sync(0xffffffffu, inc, o);
        if (lane >= o) inc += t;
    }
    if (lane == 31) sWsum[warp] = inc;
    __syncthreads();
    if (warp == 0) {
        unsigned wv = sWsum[lane];
        unsigned wi = wv;
        #pragma unroll
        for (int o = 1; o < 32; o <<= 1) {
            unsigned t = __shfl_up_sync(0xffffffffu, wi, o);
            if (lane >= o) wi += t;
        }
        sWsum[lane] = wi - wv;
    }
    __syncthreads();
    unsigned before = sWsum[warp] + inc - psum;

    unsigned c = before;
    #pragma unroll
    for (int k = 0; k < 4; k++) {
        unsigned h = cnt[k];
        if (c < TOPK && c + h >= TOPK) sT = 4095 - (4 * tid + k);
        c += h;
    }
    if (tid == 0) { sNW = 0; sNB = 0; }
    __syncthreads();

    int T = sT;
    for (int i = tid; i < NN; i += 1024) {
        unsigned long long k = keys[i];
        int bin = (int)(k >> 52);
        if (bin > T) { int pos = atomicAdd(&sNW, 1); win[pos] = k; }
        else if (bin == T) { int pos = atomicAdd(&sNB, 1); if (pos < BND_CAP) bnd[pos] = k; }
    }
    __syncthreads();
    int nB = sNB < BND_CAP ? sNB : BND_CAP;
    for (int i = tid; i < BND_CAP; i += 1024) if (i >= nB) bnd[i] = 0ULL;
    __syncthreads();

    for (int k = 2; k <= BND_CAP; k <<= 1) {
        for (int j = k >> 1; j > 0; j >>= 1) {
            #pragma unroll
            for (int h = 0; h < 2; h++) {
                int i = tid + h * 1024;
                int ixj = i ^ j;
                if (ixj > i) {
                    bool desc = ((i & k) == 0);
                    unsigned long long a = bnd[i], d = bnd[ixj];
                    bool sw = desc ? (a < d) : (a > d);
                    if (sw) { bnd[i] = d; bnd[ixj] = a; }
                }
            }
            __syncthreads();
        }
    }

    int nW = sNW;
    int need = TOPK - nW;
    for (int i = tid; i < need; i += 1024) win[nW + i] = bnd[i];
    __syncthreads();

    if (nW > 0) {
        for (int k = 2; k <= TOPK; k <<= 1) {
            for (int j = k >> 1; j > 0; j >>= 1) {
                int i = tid, ixj = i ^ j;
                if (ixj > i) {
                    bool desc = ((i & k) == 0);
                    unsigned long long a = win[i], d = win[ixj];
                    bool sw = desc ? (a < d) : (a > d);
                    if (sw) { win[i] = d; win[ixj] = a; }
                }
                __syncthreads();
            }
        }
    }

    // decode + emit
    {
        unsigned long long key = win[tid];
        unsigned u = (unsigned)(key >> 32);
        unsigned fb = (u & 0x80000000u) ? (u ^ 0x80000000u) : ~u;
        float score = __uint_as_float(fb);
        unsigned idx = ~((unsigned)(key & 0xffffffffu));

        const float* p = in + ((size_t)b * NN + idx) * STRIDE;
        float cx = p[0], cy = p[1], w = p[2], h = p[3];
        float x1 = cx - w * 0.5f, y1 = cy - h * 0.5f;
        float x2 = cx + w * 0.5f, y2 = cy + h * 0.5f;
        float cf = (float)g_cls[(size_t)b * NN + idx];
        float off = cf * MAX_WH;

        g_score [b * TOPK + tid] = score;
        g_box   [b * TOPK + tid] = make_float4(x1, y1, x2, y2);
        g_boxoff[b * TOPK + tid] = make_float4(x1 + off, y1 + off, x2 + off, y2 + off);
        g_clsf  [b * TOPK + tid] = cf;
    }
}

// =====================================================================
// Kernel C1: parallel suppression bitmatrix (upper triangle only).
// =====================================================================
__global__ void __launch_bounds__(256) iou_kernel() {
    int b = blockIdx.y;
    int tid = threadIdx.x, warp = tid >> 5, lane = tid & 31;
    __shared__ float4 cb[TOPK];
    for (int j = tid; j < TOPK; j += 256) cb[j] = g_boxoff[b * TOPK + j];
    __syncthreads();

    int i = blockIdx.x * 8 + warp;
    float4 bi = cb[i];
    float ai = (bi.z - bi.x) * (bi.w - bi.y);
    unsigned long long myw = 0;
    int s0 = i >> 5;
    #pragma unroll 4
    for (int s = s0; s < 32; s++) {
        int j = s * 32 + lane;
        float4 bj = cb[j];
        float lx = fmaxf(bi.x, bj.x);
        float ly = fmaxf(bi.y, bj.y);
        float rx = fminf(bi.z, bj.z);
        float ry = fminf(bi.w, bj.w);
        float iw = fmaxf(rx - lx, 0.0f);
        float ih = fmaxf(ry - ly, 0.0f);
        float inter = iw * ih;
        float aj = (bj.z - bj.x) * (bj.w - bj.y);
        float iou = inter / (ai + aj - inter + 1e-07f);
        bool pred = (j > i) && (iou > IOU_THR);
        unsigned bal = __ballot_sync(0xffffffffu, pred);
        if (lane == (s >> 1)) myw |= ((unsigned long long)bal) << ((s & 1) * 32);
    }
    if (lane < 16) g_mask[((size_t)b * TOPK + i) * 16 + lane] = myw;
}

// =====================================================================
// Kernel C2: word-major branch-lean greedy sweep (warp 0), full mask
// in 128KB dynamic smem, stats + det[2] + fused final reduction.
// =====================================================================
__global__ void __launch_bounds__(512) nms_kernel(float* __restrict__ out) {
    extern __shared__ unsigned long long sRows[];       // TOPK*16 words
    int b = blockIdx.x, tid = threadIdx.x, warp = tid >> 5, lane = tid & 31;
    __shared__ unsigned long long sRem[16];
    __shared__ int sKeptIdx[MAXDET];
    __shared__ int sN;
    __shared__ float sRed[16];

    {
        const ulonglong2* srcv = (const ulonglong2*)(g_mask + (size_t)b * TOPK * 16);
        ulonglong2* dstv = (ulonglong2*)sRows;
        #pragma unroll
        for (int k = 0; k < 16; k++)
            dstv[tid + k * 512] = srcv[tid + k * 512];
    }

    {
        float s0 = g_score[b * TOPK + warp * 64 + lane];
        float s1 = g_score[b * TOPK + warp * 64 + 32 + lane];
        unsigned lo = __ballot_sync(0xffffffffu, s0 <= 0.0f);
        unsigned hi = __ballot_sync(0xffffffffu, s1 <= 0.0f);
        if (lane == 0) sRem[warp] = ((unsigned long long)hi << 32) | lo;
    }
    __syncthreads();

    if (warp == 0) {
        unsigned long long remw = (lane < 16) ? sRem[lane] : ~0ULL;
        int kept = 0;
        for (int w = 0; w < 16; w++) {
            unsigned long long alive = ~__shfl_sync(0xffffffffu, remw, w);
            while (alive) {
                int bit = __ffsll((long long)alive) - 1;
                int i = (w << 6) + bit;
                if (lane == 0) sKeptIdx[kept] = i;     // predicated STS
                kept++;
                if (kept >= MAXDET) goto sweep_done;   // rare forward branch
                unsigned long long rcur = sRows[i * 16 + w];          // broadcast
                unsigned long long rown = (lane < 16) ? sRows[i * 16 + lane] : 0ULL;
                remw |= rown;                           // off-chain
                alive = (alive & (alive - 1)) & ~rcur;  // chain
            }
        }
    sweep_done:
        if (lane == 0) sN = kept;
    }
    __syncthreads();
    int n = sN;

    float contrib = 0.0f;
    float4 bbx = make_float4(0, 0, 0, 0);
    float sc = 0.0f, cf = 0.0f;
    bool emit = (tid < n);
    if (emit) {
        int i = sKeptIdx[tid];
        sc = g_score[b * TOPK + i];
        bbx = g_box[b * TOPK + i];
        cf = g_clsf[b * TOPK + i];
        contrib = (fabsf(bbx.x - bbx.z) + fabsf(bbx.y - bbx.w)) * sc;
    }

    float v = contrib;
    #pragma unroll
    for (int o = 16; o > 0; o >>= 1) v += __shfl_down_sync(0xffffffffu, v, o);
    if (lane == 0) sRed[warp] = v;
    __syncthreads();
    if (tid == 0) {
        float x = 0.0f;
        #pragma unroll
        for (int k = 0; k < 16; k++) x += sRed[k];
        int mx = n > 1 ? n : 1;
        g_bwh[b]  = (n > 0) ? (x / (2.0f * (float)mx)) : 0.0f;
        g_bmax[b] = (n > 0) ? g_score[b * TOPK + sKeptIdx[0]] : 0.0f;
    }

    if (b == 2) {
        if (emit) {
            float* row = out + 2 + tid * 6;
            row[0] = bbx.x; row[1] = bbx.y; row[2] = bbx.z; row[3] = bbx.w;
            row[4] = sc; row[5] = cf;
        }
        if (tid >= n && tid < MAXDET) {
            float* row = out + 2 + tid * 6;
            #pragma unroll
            for (int k = 0; k < 6; k++) row[k] = 0.0f;
        }
    }

    __syncthreads();
    if (tid == 0) {
        __threadfence();
        unsigned old = atomicAdd(&g_ctr, 1u);
        if (((old + 1u) % BB) == 0u) {
            float m = 0.0f, w2 = 0.0f;
            #pragma unroll
            for (int k = 0; k < BB; k++) {
                m += __ldcg(&g_bmax[k]);
                w2 += __ldcg(&g_bwh[k]);
            }
            out[0] = m / (float)BB;
            out[1] = w2 / (float)BB;
        }
    }
}

extern "C" void kernel_launch(void* const* d_in, const int* in_sizes, int n_in,
                              void* d_out, int out_size) {
    const float* in = (const float*)d_in[0];
    float* out = (float*)d_out;

    static bool attr_done = false;
    if (!attr_done) {
        cudaFuncSetAttribute(nms_kernel,
                             cudaFuncAttributeMaxDynamicSharedMemorySize,
                             TOPK * 16 * (int)sizeof(unsigned long long));
        attr_done = true;
    }

    score_kernel<<<BB * NN / (8 * PASSES), 256>>>(in);  // 12600 blocks
    select_kernel<<<BB, 1024>>>(in);
    iou_kernel<<<dim3(TOPK / 8, BB), 256>>>();
    nms_kernel<<<BB, 512, TOPK * 16 * sizeof(unsigned long long)>>>(out);
}

// round 14
// speedup vs baseline: 1.3333x; 1.0129x over previous
#include <cuda_runtime.h>
#include <cstdint>

#define BB 16
#define NN 25200
#define NCLS 80
#define STRIDE 85
#define TOPK 1024
#define MAXDET 300
#define CONF_THRES 0.25f
#define IOU_THR 0.45f
#define MAX_WH 7680.0f
#define BND_CAP 2048
#define PASSES 4            // anchors per warp per block
#define NCHUNK 8            // nms mask pipeline chunks (16KB each)

// -------- scratch (device globals, no allocations) --------
__device__ unsigned long long g_keys[BB * NN];
__device__ unsigned char     g_cls[BB * NN];
__device__ float  g_score [BB * TOPK];
__device__ float4 g_box   [BB * TOPK];   // un-offset xyxy
__device__ float4 g_boxoff[BB * TOPK];   // class-offset xyxy
__device__ float  g_clsf  [BB * TOPK];
__device__ unsigned long long g_mask[(size_t)BB * TOPK * 16]; // suppression bitmatrix
__device__ float  g_bmax[BB];
__device__ float  g_bwh [BB];
__device__ unsigned g_ctr;               // never reset: modulo trigger

__device__ __forceinline__ unsigned smem_u32(const void* p) {
    return (unsigned)__cvta_generic_to_shared(p);
}

// =====================================================================
// Kernel A: warp-per-anchor DIRECT from global (no smem staging).
// =====================================================================
__global__ void __launch_bounds__(256) score_kernel(const float* __restrict__ in) {
    int tid = threadIdx.x, warp = tid >> 5, lane = tid & 31;
    int base = blockIdx.x * (8 * PASSES);

    #pragma unroll
    for (int pass = 0; pass < PASSES; pass++) {
        int gidx = base + pass * 8 + warp;
        const float* p = in + (size_t)gidx * STRIDE;

        float v0 = p[lane];
        float v1 = p[lane + 32];
        float v2 = (lane < STRIDE - 64) ? p[lane + 64] : 0.0f;
        float obj = __shfl_sync(0xffffffffu, v0, 4);

        float score = -1.0f;
        int cls = 0;
        if (obj > CONF_THRES) {               // warp-uniform branch
            float best = -1.0f; int bidx = 1 << 24;
            if (lane >= 5) {
                float pr = v0 * obj;
                if (pr > best) { best = pr; bidx = lane - 5; }
            }
            {
                float pr = v1 * obj; int ci = lane + 27;
                if (pr > best) { best = pr; bidx = ci; }
            }
            if (lane < 21) {
                float pr = v2 * obj; int ci = lane + 59;
                if (pr > best) { best = pr; bidx = ci; }
            }
            unsigned mybits = __float_as_uint(best);
            unsigned vmax = __reduce_max_sync(0xffffffffu, mybits);
            unsigned cand = (mybits == vmax) ? (unsigned)bidx : 0xFFFFFFFFu;
            unsigned cmin = __reduce_min_sync(0xffffffffu, cand);
            float conf = __uint_as_float(vmax);
            cls = (int)cmin;
            score = (conf > CONF_THRES) ? conf : -1.0f;
        }
        if (lane == 0) {
            unsigned u = __float_as_uint(score);
            u = (u & 0x80000000u) ? ~u : (u | 0x80000000u);
            unsigned anchor = (unsigned)(gidx % NN);
            g_keys[gidx] = ((unsigned long long)u << 32) | (unsigned)(~anchor);
            g_cls[gidx] = (unsigned char)cls;
        }
    }
}

// =====================================================================
// Kernel B: per-batch exact sorted top-1024 (12-bit radix + bitonic).
// =====================================================================
__global__ void __launch_bounds__(1024) select_kernel(const float* __restrict__ in) {
    int b = blockIdx.x;
    int tid = threadIdx.x;
    int warp = tid >> 5, lane = tid & 31;

    __shared__ unsigned hist[4096];
    __shared__ unsigned sWsum[32];
    __shared__ unsigned long long win[TOPK];
    __shared__ unsigned long long bnd[BND_CAP];
    __shared__ int sT, sNW, sNB;

    const unsigned long long* keys = g_keys + (size_t)b * NN;

    for (int i = tid; i < 4096; i += 1024) hist[i] = 0;
    __syncthreads();
    for (int i = tid; i < NN; i += 1024) {
        unsigned bin = (unsigned)(keys[i] >> 52);
        atomicAdd(&hist[bin], 1u);
    }
    __syncthreads();

    unsigned cnt[4]; unsigned psum = 0;
    #pragma unroll
    for (int k = 0; k < 4; k++) { cnt[k] = hist[4095 - (4 * tid + k)]; psum += cnt[k]; }
    unsigned inc = psum;
    #pragma unroll
    for (int o = 1; o < 32; o <<= 1) {
        unsigned t = __shfl_up_sync(0xffffffffu, inc, o);
        if (lane >= o) inc += t;
    }
    if (lane == 31) sWsum[warp] = inc;
    __syncthreads();
    if (warp == 0) {
        unsigned wv = sWsum[lane];
        unsigned wi = wv;
        #pragma unroll
        for (int o = 1; o < 32; o <<= 1) {
            unsigned t = __shfl_up_sync(0xffffffffu, wi, o);
            if (lane >= o) wi += t;
        }
        sWsum[lane] = wi - wv;
    }
    __syncthreads();
    unsigned before = sWsum[warp] + inc - psum;

    unsigned c = before;
    #pragma unroll
    for (int k = 0; k < 4; k++) {
        unsigned h = cnt[k];
        if (c < TOPK && c + h >= TOPK) sT = 4095 - (4 * tid + k);
        c += h;
    }
    if (tid == 0) { sNW = 0; sNB = 0; }
    __syncthreads();

    int T = sT;
    for (int i = tid; i < NN; i += 1024) {
        unsigned long long k = keys[i];
        int bin = (int)(k >> 52);
        if (bin > T) { int pos = atomicAdd(&sNW, 1); win[pos] = k; }
        else if (bin == T) { int pos = atomicAdd(&sNB, 1); if (pos < BND_CAP) bnd[pos] = k; }
    }
    __syncthreads();
    int nB = sNB < BND_CAP ? sNB : BND_CAP;
    for (int i = tid; i < BND_CAP; i += 1024) if (i >= nB) bnd[i] = 0ULL;
    __syncthreads();

    for (int k = 2; k <= BND_CAP; k <<= 1) {
        for (int j = k >> 1; j > 0; j >>= 1) {
            #pragma unroll
            for (int h = 0; h < 2; h++) {
                int i = tid + h * 1024;
                int ixj = i ^ j;
                if (ixj > i) {
                    bool desc = ((i & k) == 0);
                    unsigned long long a = bnd[i], d = bnd[ixj];
                    bool sw = desc ? (a < d) : (a > d);
                    if (sw) { bnd[i] = d; bnd[ixj] = a; }
                }
            }
            __syncthreads();
        }
    }

    int nW = sNW;
    int need = TOPK - nW;
    for (int i = tid; i < need; i += 1024) win[nW + i] = bnd[i];
    __syncthreads();

    if (nW > 0) {
        for (int k = 2; k <= TOPK; k <<= 1) {
            for (int j = k >> 1; j > 0; j >>= 1) {
                int i = tid, ixj = i ^ j;
                if (ixj > i) {
                    bool desc = ((i & k) == 0);
                    unsigned long long a = win[i], d = win[ixj];
                    bool sw = desc ? (a < d) : (a > d);
                    if (sw) { win[i] = d; win[ixj] = a; }
                }
                __syncthreads();
            }
        }
    }

    // decode + emit
    {
        unsigned long long key = win[tid];
        unsigned u = (unsigned)(key >> 32);
        unsigned fb = (u & 0x80000000u) ? (u ^ 0x80000000u) : ~u;
        float score = __uint_as_float(fb);
        unsigned idx = ~((unsigned)(key & 0xffffffffu));

        const float* p = in + ((size_t)b * NN + idx) * STRIDE;
        float cx = p[0], cy = p[1], w = p[2], h = p[3];
        float x1 = cx - w * 0.5f, y1 = cy - h * 0.5f;
        float x2 = cx + w * 0.5f, y2 = cy + h * 0.5f;
        float cf = (float)g_cls[(size_t)b * NN + idx];
        float off = cf * MAX_WH;

        g_score [b * TOPK + tid] = score;
        g_box   [b * TOPK + tid] = make_float4(x1, y1, x2, y2);
        g_boxoff[b * TOPK + tid] = make_float4(x1 + off, y1 + off, x2 + off, y2 + off);
        g_clsf  [b * TOPK + tid] = cf;
    }
}

// =====================================================================
// Kernel C1: parallel suppression bitmatrix (upper triangle only).
// =====================================================================
__global__ void __launch_bounds__(256) iou_kernel() {
    int b = blockIdx.y;
    int tid = threadIdx.x, warp = tid >> 5, lane = tid & 31;
    __shared__ float4 cb[TOPK];
    for (int j = tid; j < TOPK; j += 256) cb[j] = g_boxoff[b * TOPK + j];
    __syncthreads();

    int i = blockIdx.x * 8 + warp;
    float4 bi = cb[i];
    float ai = (bi.z - bi.x) * (bi.w - bi.y);
    unsigned long long myw = 0;
    int s0 = i >> 5;
    #pragma unroll 4
    for (int s = s0; s < 32; s++) {
        int j = s * 32 + lane;
        float4 bj = cb[j];
        float lx = fmaxf(bi.x, bj.x);
        float ly = fmaxf(bi.y, bj.y);
        float rx = fminf(bi.z, bj.z);
        float ry = fminf(bi.w, bj.w);
        float iw = fmaxf(rx - lx, 0.0f);
        float ih = fmaxf(ry - ly, 0.0f);
        float inter = iw * ih;
        float aj = (bj.z - bj.x) * (bj.w - bj.y);
        float iou = inter / (ai + aj - inter + 1e-07f);
        bool pred = (j > i) && (iou > IOU_THR);
        unsigned bal = __ballot_sync(0xffffffffu, pred);
        if (lane == (s >> 1)) myw |= ((unsigned long long)bal) << ((s & 1) * 32);
    }
    if (lane < 16) g_mask[((size_t)b * TOPK + i) * 16 + lane] = myw;
}

// =====================================================================
// Kernel C2: greedy sweep with cp.async.bulk chunked mask pipeline.
// 8 x 16KB chunks (128 rows each); warp 0 waits per-chunk as the
// ascending sweep crosses 128-row boundaries (word w even -> chunk w/2).
// =====================================================================
__global__ void __launch_bounds__(512) nms_kernel(float* __restrict__ out) {
    extern __shared__ unsigned long long sRows[];       // TOPK*16 words (128KB)
    int b = blockIdx.x, tid = threadIdx.x, warp = tid >> 5, lane = tid & 31;
    __shared__ __align__(8) unsigned long long sMbar[NCHUNK];
    __shared__ unsigned long long sRem[16];
    __shared__ int sKeptIdx[MAXDET];
    __shared__ int sN;
    __shared__ float sRed[16];

    // issue chunked bulk copies (single thread; no per-thread LDG cost)
    if (tid == 0) {
        #pragma unroll
        for (int c = 0; c < NCHUNK; c++) {
            unsigned mb = smem_u32(&sMbar[c]);
            asm volatile("mbarrier.init.shared.b64 [%0], 1;" :: "r"(mb) : "memory");
        }
        asm volatile("fence.proxy.async.shared::cta;" ::: "memory");
        const char* src = (const char*)(g_mask + (size_t)b * TOPK * 16);
        unsigned dst = smem_u32(sRows);
        #pragma unroll
        for (int c = 0; c < NCHUNK; c++) {
            unsigned mb = smem_u32(&sMbar[c]);
            asm volatile("mbarrier.arrive.expect_tx.shared.b64 _, [%0], %1;"
                         :: "r"(mb), "r"(16384u) : "memory");
            asm volatile("cp.async.bulk.shared::cta.global.mbarrier::complete_tx::bytes [%0], [%1], %2, [%3];"
                         :: "r"(dst + c * 16384u), "l"(src + (size_t)c * 16384),
                            "r"(16384u), "r"(mb) : "memory");
        }
    }

    // init removed bitmap: 16 warps each build one 64-bit word via ballots
    {
        float s0 = g_score[b * TOPK + warp * 64 + lane];
        float s1 = g_score[b * TOPK + warp * 64 + 32 + lane];
        unsigned lo = __ballot_sync(0xffffffffu, s0 <= 0.0f);
        unsigned hi = __ballot_sync(0xffffffffu, s1 <= 0.0f);
        if (lane == 0) sRem[warp] = ((unsigned long long)hi << 32) | lo;
    }
    __syncthreads();   // sRem + mbarrier inits visible

    if (warp == 0) {
        unsigned long long remw = (lane < 16) ? sRem[lane] : ~0ULL;
        int kept = 0;
        for (int w = 0; w < 16; w++) {
            if ((w & 1) == 0) {   // wait for chunk w/2 (rows 64w .. 64w+127)
                unsigned mb = smem_u32(&sMbar[w >> 1]);
                unsigned done;
                asm volatile(
                    "{\n\t.reg .pred p;\n\t"
                    "mbarrier.try_wait.parity.acquire.cta.shared::cta.b64 p, [%1], 0;\n\t"
                    "selp.b32 %0, 1, 0, p;\n\t}"
                    : "=r"(done) : "r"(mb) : "memory");
                while (!done) {
                    asm volatile(
                        "{\n\t.reg .pred p;\n\t"
                        "mbarrier.try_wait.parity.acquire.cta.shared::cta.b64 p, [%1], 0, 0x989680;\n\t"
                        "selp.b32 %0, 1, 0, p;\n\t}"
                        : "=r"(done) : "r"(mb) : "memory");
                }
            }
            unsigned long long alive = ~__shfl_sync(0xffffffffu, remw, w);
            while (alive) {
                int bit = __ffsll((long long)alive) - 1;
                int i = (w << 6) + bit;
                if (lane == 0) sKeptIdx[kept] = i;     // predicated STS
                kept++;
                if (kept >= MAXDET) goto sweep_done;
                unsigned long long rcur = sRows[i * 16 + w];          // broadcast
                unsigned long long rown = (lane < 16) ? sRows[i * 16 + lane] : 0ULL;
                remw |= rown;                           // off-chain
                alive = (alive & (alive - 1)) & ~rcur;  // chain
            }
        }
    sweep_done:
        if (lane == 0) sN = kept;
    }
    __syncthreads();
    int n = sN;

    float contrib = 0.0f;
    float4 bbx = make_float4(0, 0, 0, 0);
    float sc = 0.0f, cf = 0.0f;
    bool emit = (tid < n);
    if (emit) {
        int i = sKeptIdx[tid];
        sc = g_score[b * TOPK + i];
        bbx = g_box[b * TOPK + i];
        cf = g_clsf[b * TOPK + i];
        contrib = (fabsf(bbx.x - bbx.z) + fabsf(bbx.y - bbx.w)) * sc;
    }

    float v = contrib;
    #pragma unroll
    for (int o = 16; o > 0; o >>= 1) v += __shfl_down_sync(0xffffffffu, v, o);
    if (lane == 0) sRed[warp] = v;
    __syncthreads();
    if (tid == 0) {
        float x = 0.0f;
        #pragma unroll
        for (int k = 0; k < 16; k++) x += sRed[k];
        int mx = n > 1 ? n : 1;
        g_bwh[b]  = (n > 0) ? (x / (2.0f * (float)mx)) : 0.0f;
        g_bmax[b] = (n > 0) ? g_score[b * TOPK + sKeptIdx[0]] : 0.0f;
    }

    if (b == 2) {
        if (emit) {
            float* row = out + 2 + tid * 6;
            row[0] = bbx.x; row[1] = bbx.y; row[2] = bbx.z; row[3] = bbx.w;
            row[4] = sc; row[5] = cf;
        }
        if (tid >= n && tid < MAXDET) {
            float* row = out + 2 + tid * 6;
            #pragma unroll
            for (int k = 0; k < 6; k++) row[k] = 0.0f;
        }
    }

    __syncthreads();
    if (tid == 0) {
        __threadfence();
        unsigned old = atomicAdd(&g_ctr, 1u);
        if (((old + 1u) % BB) == 0u) {
            float m = 0.0f, w2 = 0.0f;
            #pragma unroll
            for (int k = 0; k < BB; k++) {
                m += __ldcg(&g_bmax[k]);
                w2 += __ldcg(&g_bwh[k]);
            }
            out[0] = m / (float)BB;
            out[1] = w2 / (float)BB;
        }
    }
}

extern "C" void kernel_launch(void* const* d_in, const int* in_sizes, int n_in,
                              void* d_out, int out_size) {
    const float* in = (const float*)d_in[0];
    float* out = (float*)d_out;

    static bool attr_done = false;
    if (!attr_done) {
        cudaFuncSetAttribute(nms_kernel,
                             cudaFuncAttributeMaxDynamicSharedMemorySize,
                             TOPK * 16 * (int)sizeof(unsigned long long));
        attr_done = true;
    }

    score_kernel<<<BB * NN / (8 * PASSES), 256>>>(in);  // 12600 blocks
    select_kernel<<<BB, 1024>>>(in);
    iou_kernel<<<dim3(TOPK / 8, BB), 256>>>();
    nms_kernel<<<BB, 512, TOPK * 16 * sizeof(unsigned long long)>>>(out);
}